// round 5
// baseline (speedup 1.0000x reference)
#include <cuda_runtime.h>
#include <cstdint>

// ---------------------------------------------------------------------------
// MetaMLP (3-step GraphNet) on GB300 — mma.sync edge GEMM + CSR aggregation.
// ---------------------------------------------------------------------------

#define D 128
static constexpr int N_NODES  = 50000;
static constexpr int N_EDGES  = 800000;
static constexpr int N_GRAPHS = 16;
static constexpr int OUTW     = 4 * D;          // 512 output cols per row
static constexpr int N_TILES  = N_EDGES / 128;  // 6250

typedef unsigned long long u64;

// ------------------------- device scratch (no allocs) ----------------------
__device__ float g_ea  [(size_t)N_EDGES  * D];
__device__ float g_P12 [(size_t)N_NODES  * 2 * D];   // [P1+u+b | P2]
__device__ float g_u    [N_GRAPHS * D];
__device__ float g_uW4b [N_GRAPHS * D];
__device__ float g_uWn3b[N_GRAPHS * D];
__device__ float g_gsum [N_GRAPHS * D];
__device__ float g_invN [N_NODES];
__device__ float g_invG [N_GRAPHS];
__device__ int   g_cnt  [N_NODES];
__device__ int   g_rowptr[N_NODES + 1];
__device__ int   g_off  [N_NODES];
__device__ int   g_perm [N_EDGES];

// ------------------------------ helpers ------------------------------------
__device__ __forceinline__ u64 pack2(float a, float b) {
    u64 r; asm("mov.b64 %0, {%1, %2};" : "=l"(r) : "f"(a), "f"(b)); return r;
}
__device__ __forceinline__ float2 unpack2(u64 v) {
    float2 r; asm("mov.b64 {%0, %1}, %2;" : "=f"(r.x), "=f"(r.y) : "l"(v)); return r;
}
__device__ __forceinline__ void ffma2(u64& d, u64 a, u64 b) {
    asm("fma.rn.f32x2 %0, %1, %2, %3;" : "=l"(d) : "l"(a), "l"(b), "l"(d));
}
__device__ __forceinline__ uint32_t cvt_bf16x2(float a, float b) {
    uint32_t r;
    asm("cvt.rn.bf16x2.f32 %0, %1, %2;" : "=r"(r) : "f"(b), "f"(a));
    return r;
}
__device__ __forceinline__ void split2(float x, float y, uint32_t& hi, uint32_t& lo) {
    hi = cvt_bf16x2(x, y);
    float hx = __uint_as_float(hi << 16);
    float hy = __uint_as_float(hi & 0xffff0000u);
    lo = cvt_bf16x2(x - hx, y - hy);
}
__device__ __forceinline__ void mma_bf16(float* d, const uint32_t* a, uint32_t b0, uint32_t b1) {
    asm volatile("mma.sync.aligned.m16n8k16.row.col.f32.bf16.bf16.f32 "
        "{%0,%1,%2,%3}, {%4,%5,%6,%7}, {%8,%9}, {%0,%1,%2,%3};"
        : "+f"(d[0]), "+f"(d[1]), "+f"(d[2]), "+f"(d[3])
        : "r"(a[0]), "r"(a[1]), "r"(a[2]), "r"(a[3]), "r"(b0), "r"(b1));
}

// ------------------------------ init / CSR ----------------------------------
__global__ void init_kernel(const float* __restrict__ x, const float* __restrict__ u,
                            float* __restrict__ out_x, float* __restrict__ out_g) {
    int stride = gridDim.x * blockDim.x;
    int tid0 = blockIdx.x * blockDim.x + threadIdx.x;
    for (int i = tid0; i < N_NODES * D; i += stride) {
        int r = i >> 7, c = i & (D - 1);
        out_x[(size_t)r * OUTW + c] = x[i];
    }
    for (int i = tid0; i < N_GRAPHS * D; i += stride) {
        int r = i >> 7, c = i & (D - 1);
        out_g[(size_t)r * OUTW + c] = u[i];
        g_u[i] = u[i];
    }
    for (int i = tid0; i < N_NODES; i += stride) g_cnt[i] = 0;
    for (int i = tid0; i < N_GRAPHS; i += stride) g_invG[i] = 0.f;
}

__global__ void hist_kernel(const int* __restrict__ dst, const int* __restrict__ batch) {
    int stride = gridDim.x * blockDim.x;
    int tid0 = blockIdx.x * blockDim.x + threadIdx.x;
    for (int i = tid0; i < N_EDGES; i += stride) atomicAdd(&g_cnt[dst[i]], 1);
    for (int i = tid0; i < N_NODES; i += stride) atomicAdd(&g_invG[batch[i]], 1.f);
}

__global__ void finalize_counts_kernel() {
    int stride = gridDim.x * blockDim.x;
    int tid0 = blockIdx.x * blockDim.x + threadIdx.x;
    for (int i = tid0; i < N_NODES; i += stride)
        g_invN[i] = 1.f / fmaxf((float)g_cnt[i], 1.f);
    for (int i = tid0; i < N_GRAPHS; i += stride) g_invG[i] = 1.f / fmaxf(g_invG[i], 1.f);
}

// single-block exclusive scan of g_cnt -> g_rowptr / g_off
__global__ void scan_kernel() {
    __shared__ int part[1024];
    const int NPT = (N_NODES + 1023) / 1024;   // 49
    int t = threadIdx.x;
    int base = t * NPT;
    int s = 0;
    for (int i = 0; i < NPT; i++) {
        int idx = base + i;
        if (idx < N_NODES) s += g_cnt[idx];
    }
    part[t] = s;
    __syncthreads();
    for (int off = 1; off < 1024; off <<= 1) {
        int v = (t >= off) ? part[t - off] : 0;
        __syncthreads();
        part[t] += v;
        __syncthreads();
    }
    int run = (t > 0) ? part[t - 1] : 0;
    for (int i = 0; i < NPT; i++) {
        int idx = base + i;
        if (idx < N_NODES) {
            g_rowptr[idx] = run;
            g_off[idx] = run;
            run += g_cnt[idx];
        }
    }
    if (t == 1023) g_rowptr[N_NODES] = part[1023];
}

__global__ void scatter_kernel(const int* __restrict__ dst) {
    int stride = gridDim.x * blockDim.x;
    for (int e = blockIdx.x * blockDim.x + threadIdx.x; e < N_EDGES; e += stride) {
        int p = atomicAdd(&g_off[dst[e]], 1);
        g_perm[p] = e;
    }
}

// ------------------------ per-step small precompute -------------------------
__global__ void prep_u_kernel(const float* __restrict__ W_edge, const float* __restrict__ b_edge,
                              const float* __restrict__ W_node, const float* __restrict__ b_node) {
    int g = blockIdx.x >> 1, sel = blockIdx.x & 1;
    __shared__ float su[D];
    int j = threadIdx.x;
    su[j] = g_u[g * D + j];
    __syncthreads();
    const float* W = sel ? (W_node + 2 * D * D) : (W_edge + 3 * D * D);
    float acc = sel ? b_node[j] : b_edge[j];
#pragma unroll 8
    for (int k = 0; k < D; k++) acc = fmaf(su[k], W[k * D + j], acc);
    if (sel) {
        g_uWn3b[g * D + j] = acc;
    } else {
        g_uW4b[g * D + j] = acc;
        g_gsum[g * D + j] = 0.f;
    }
}

// ----------------- fused P1/P2 dense matvec (K=128, FFMA2) ------------------
__global__ void __launch_bounds__(256) matvec_P_kernel(
    const float* __restrict__ X, const float* __restrict__ W_edge,
    const int* __restrict__ batch) {
    extern __shared__ float sh[];
    float* sW1 = sh;
    float* sW2 = sh + D * D;
    float* sV  = sh + 2 * D * D;
    for (int i = threadIdx.x; i < D * D; i += blockDim.x) {
        sW1[i] = W_edge[i];
        sW2[i] = W_edge[D * D + i];
    }
    __syncthreads();
    int warp = threadIdx.x >> 5, lane = threadIdx.x & 31;
    float* myV = sV + warp * 8 * D;
    const int groups = N_NODES / 8;
    for (int grp = blockIdx.x * 8 + warp; grp < groups; grp += gridDim.x * 8) {
        int r0 = grp * 8;
#pragma unroll
        for (int e = 0; e < 8; e++) {
            float4 v = *((const float4*)(X + (size_t)(r0 + e) * OUTW) + lane);
            *((float4*)(myV + e * D) + lane) = v;
        }
        __syncwarp();
        u64 a0[8], a1[8], b0[8], b1[8];
#pragma unroll
        for (int e = 0; e < 8; e++) { a0[e] = a1[e] = b0[e] = b1[e] = 0ull; }
        for (int k = 0; k < D; k += 4) {
            ulonglong2 u0 = *((const ulonglong2*)(sW1 + (k + 0) * D) + lane);
            ulonglong2 u1 = *((const ulonglong2*)(sW1 + (k + 1) * D) + lane);
            ulonglong2 u2 = *((const ulonglong2*)(sW1 + (k + 2) * D) + lane);
            ulonglong2 u3 = *((const ulonglong2*)(sW1 + (k + 3) * D) + lane);
            ulonglong2 v0 = *((const ulonglong2*)(sW2 + (k + 0) * D) + lane);
            ulonglong2 v1 = *((const ulonglong2*)(sW2 + (k + 1) * D) + lane);
            ulonglong2 v2 = *((const ulonglong2*)(sW2 + (k + 2) * D) + lane);
            ulonglong2 v3 = *((const ulonglong2*)(sW2 + (k + 3) * D) + lane);
#pragma unroll
            for (int e = 0; e < 8; e++) {
                float4 a = *(const float4*)(myV + e * D + k);
                u64 p;
                p = pack2(a.x, a.x);
                ffma2(a0[e], p, u0.x); ffma2(a1[e], p, u0.y);
                ffma2(b0[e], p, v0.x); ffma2(b1[e], p, v0.y);
                p = pack2(a.y, a.y);
                ffma2(a0[e], p, u1.x); ffma2(a1[e], p, u1.y);
                ffma2(b0[e], p, v1.x); ffma2(b1[e], p, v1.y);
                p = pack2(a.z, a.z);
                ffma2(a0[e], p, u2.x); ffma2(a1[e], p, u2.y);
                ffma2(b0[e], p, v2.x); ffma2(b1[e], p, v2.y);
                p = pack2(a.w, a.w);
                ffma2(a0[e], p, u3.x); ffma2(a1[e], p, u3.y);
                ffma2(b0[e], p, v3.x); ffma2(b1[e], p, v3.y);
            }
        }
#pragma unroll
        for (int e = 0; e < 8; e++) {
            int g = __ldg(batch + r0 + e);
            float4 uv = *((const float4*)(g_uW4b + g * D) + lane);
            float2 r01 = unpack2(a0[e]), r23 = unpack2(a1[e]);
            float2 s01 = unpack2(b0[e]), s23 = unpack2(b1[e]);
            float* base = g_P12 + (size_t)(r0 + e) * (2 * D);
            *((float4*)base + lane) =
                make_float4(r01.x + uv.x, r01.y + uv.y, r23.x + uv.z, r23.y + uv.w);
            *((float4*)(base + D) + lane) = make_float4(s01.x, s01.y, s23.x, s23.y);
        }
        __syncwarp();
    }
}

// ------------------------- edge kernel: mma.sync ----------------------------
// ea' = relu(ea@We3 + P1'[src] + P2[dst]); no atomics (CSR agg in node kernel)
__global__ void __launch_bounds__(256, 2) edge_mma_kernel(
    int use_ext, const float* __restrict__ ext_ea,
    const int* __restrict__ src, const int* __restrict__ dst,
    const float* __restrict__ We3) {
    extern __shared__ uint4 sB[];   // [nt=16][ks=8][lane=32] -> {b0hi,b1hi,b0lo,b1lo}
    int tid = threadIdx.x;

    for (int i = tid; i < 16 * 8 * 32; i += 256) {
        int lane = i & 31, ks = (i >> 5) & 7, nt = i >> 8;
        int gid = lane >> 2, tig = lane & 3;
        int n  = nt * 8 + gid;
        int k0 = ks * 16 + tig * 2;
        float w00 = __ldg(We3 + k0 * D + n);
        float w01 = __ldg(We3 + (k0 + 1) * D + n);
        float w10 = __ldg(We3 + (k0 + 8) * D + n);
        float w11 = __ldg(We3 + (k0 + 9) * D + n);
        uint32_t b0h, b0l, b1h, b1l;
        split2(w00, w01, b0h, b0l);
        split2(w10, w11, b1h, b1l);
        sB[i] = make_uint4(b0h, b1h, b0l, b1l);
    }
    __syncthreads();

    int wid = tid >> 5, lane = tid & 31;
    int gid = lane >> 2, tig = lane & 3;
    int wm = wid & 3, wn = wid >> 2;
    const float* ea_in = use_ext ? ext_ea : (const float*)g_ea;

    for (int tile = blockIdx.x; tile < N_TILES; tile += gridDim.x) {
        const float* A = ea_in + (size_t)tile * (128 * 128);
        float acc[2][8][4];
#pragma unroll
        for (int mt = 0; mt < 2; mt++)
#pragma unroll
            for (int nt = 0; nt < 8; nt++)
#pragma unroll
                for (int q = 0; q < 4; q++) acc[mt][nt][q] = 0.f;

#pragma unroll
        for (int ks = 0; ks < 8; ks++) {
            uint32_t ah[2][4], al[2][4];
#pragma unroll
            for (int mt = 0; mt < 2; mt++) {
                const float* p = A + (wm * 32 + mt * 16 + gid) * 128 + ks * 16 + tig * 2;
                float2 v0 = __ldg((const float2*)p);
                float2 v1 = __ldg((const float2*)(p + 8 * 128));
                float2 v2 = __ldg((const float2*)(p + 8));
                float2 v3 = __ldg((const float2*)(p + 8 * 128 + 8));
                split2(v0.x, v0.y, ah[mt][0], al[mt][0]);
                split2(v1.x, v1.y, ah[mt][1], al[mt][1]);
                split2(v2.x, v2.y, ah[mt][2], al[mt][2]);
                split2(v3.x, v3.y, ah[mt][3], al[mt][3]);
            }
#pragma unroll
            for (int nt = 0; nt < 8; nt++) {
                uint4 b = sB[((wn * 8 + nt) * 8 + ks) * 32 + lane];
#pragma unroll
                for (int mt = 0; mt < 2; mt++) {
                    mma_bf16(acc[mt][nt], ah[mt], b.x, b.y);   // Ahi * Whi
                    mma_bf16(acc[mt][nt], ah[mt], b.z, b.w);   // Ahi * Wlo
                    mma_bf16(acc[mt][nt], al[mt], b.x, b.y);   // Alo * Whi
                }
            }
        }

#pragma unroll
        for (int mt = 0; mt < 2; mt++) {
#pragma unroll
            for (int h = 0; h < 2; h++) {
                int r = tile * 128 + wm * 32 + mt * 16 + h * 8 + gid;
                int s = __ldg(src + r), d = __ldg(dst + r);
                const float* p1b = g_P12 + (size_t)s * 256;
                const float* p2b = g_P12 + (size_t)d * 256 + 128;
                float* eo = g_ea + (size_t)r * 128;
#pragma unroll
                for (int nt = 0; nt < 8; nt++) {
                    int c = wn * 64 + nt * 8 + tig * 2;
                    float2 p1 = __ldg((const float2*)(p1b + c));
                    float2 p2 = __ldg((const float2*)(p2b + c));
                    float rx = fmaxf(acc[mt][nt][h * 2 + 0] + p1.x + p2.x, 0.f);
                    float ry = fmaxf(acc[mt][nt][h * 2 + 1] + p1.y + p2.y, 0.f);
                    *(float2*)(eo + c) = make_float2(rx, ry);
                }
            }
        }
    }
}

// ------------------------------- node kernel -------------------------------
// x' = relu([x, csr_mean(ea')] @ Wn12 + uWn3b[batch]); per-graph sums
__global__ void __launch_bounds__(256) node_kernel(
    const float* __restrict__ Xin, float* __restrict__ Xout,
    const int* __restrict__ batch, const float* __restrict__ W_node) {
    extern __shared__ float sh[];
    float* sW = sh;
    float* sU = sh + 2 * D * D;
    float* sV = sU + N_GRAPHS * D;
    for (int i = threadIdx.x; i < 2 * D * D; i += blockDim.x) sW[i] = W_node[i];
    for (int i = threadIdx.x; i < N_GRAPHS * D; i += blockDim.x) sU[i] = g_uWn3b[i];
    __syncthreads();
    int warp = threadIdx.x >> 5, lane = threadIdx.x & 31;
    float* myV = sV + warp * 8 * (2 * D);
    const int groups = N_NODES / 8;
    for (int grp = blockIdx.x * 8 + warp; grp < groups; grp += gridDim.x * 8) {
        int r0 = grp * 8;
#pragma unroll
        for (int e = 0; e < 8; e++) {
            int row = r0 + e;
            float4 xv = *((const float4*)(Xin + (size_t)row * OUTW) + lane);
            *((float4*)(myV + e * 2 * D) + lane) = xv;
            // CSR mean of incoming edge features
            int beg = __ldg(&g_rowptr[row]);
            int end = __ldg(&g_rowptr[row + 1]);
            float4 av = make_float4(0.f, 0.f, 0.f, 0.f);
            int j = beg;
            for (; j + 1 < end; j += 2) {
                int e0 = __ldg(&g_perm[j]);
                int e1 = __ldg(&g_perm[j + 1]);
                float4 v0 = __ldg((const float4*)(g_ea + (size_t)e0 * D) + lane);
                float4 v1 = __ldg((const float4*)(g_ea + (size_t)e1 * D) + lane);
                av.x += v0.x + v1.x; av.y += v0.y + v1.y;
                av.z += v0.z + v1.z; av.w += v0.w + v1.w;
            }
            if (j < end) {
                int e0 = __ldg(&g_perm[j]);
                float4 v0 = __ldg((const float4*)(g_ea + (size_t)e0 * D) + lane);
                av.x += v0.x; av.y += v0.y; av.z += v0.z; av.w += v0.w;
            }
            float inv = __ldg(&g_invN[row]);
            av.x *= inv; av.y *= inv; av.z *= inv; av.w *= inv;
            *((float4*)(myV + e * 2 * D + D) + lane) = av;
        }
        __syncwarp();
        u64 acc0[8], acc1[8];
#pragma unroll
        for (int e = 0; e < 8; e++) { acc0[e] = 0ull; acc1[e] = 0ull; }
        for (int k = 0; k < 2 * D; k += 4) {
            ulonglong2 w0 = *((const ulonglong2*)(sW + (k + 0) * D) + lane);
            ulonglong2 w1 = *((const ulonglong2*)(sW + (k + 1) * D) + lane);
            ulonglong2 w2 = *((const ulonglong2*)(sW + (k + 2) * D) + lane);
            ulonglong2 w3 = *((const ulonglong2*)(sW + (k + 3) * D) + lane);
#pragma unroll
            for (int e = 0; e < 8; e++) {
                float4 a = *(const float4*)(myV + e * 2 * D + k);
                u64 p;
                p = pack2(a.x, a.x); ffma2(acc0[e], p, w0.x); ffma2(acc1[e], p, w0.y);
                p = pack2(a.y, a.y); ffma2(acc0[e], p, w1.x); ffma2(acc1[e], p, w1.y);
                p = pack2(a.z, a.z); ffma2(acc0[e], p, w2.x); ffma2(acc1[e], p, w2.y);
                p = pack2(a.w, a.w); ffma2(acc0[e], p, w3.x); ffma2(acc1[e], p, w3.y);
            }
        }
#pragma unroll
        for (int e = 0; e < 8; e++) {
            int row = r0 + e;
            int g = __ldg(batch + row);
            float4 ub = *((const float4*)(sU + g * D) + lane);
            float2 c01 = unpack2(acc0[e]), c23 = unpack2(acc1[e]);
            float4 r;
            r.x = fmaxf(c01.x + ub.x, 0.f);
            r.y = fmaxf(c01.y + ub.y, 0.f);
            r.z = fmaxf(c23.x + ub.z, 0.f);
            r.w = fmaxf(c23.y + ub.w, 0.f);
            *((float4*)(Xout + (size_t)row * OUTW) + lane) = r;
            atomicAdd((float4*)(g_gsum + g * D) + lane, r);
        }
        __syncwarp();
    }
}

// ------------------------------ global kernel ------------------------------
__global__ void global_kernel(const float* __restrict__ W_glob,
                              const float* __restrict__ b_glob,
                              float* __restrict__ out_g) {
    int g = blockIdx.x;
    int j = threadIdx.x;
    __shared__ float su[D], sm[D];
    su[j] = g_u[g * D + j];
    sm[j] = g_gsum[g * D + j] * g_invG[g];
    __syncthreads();
    float acc = b_glob[j];
#pragma unroll 4
    for (int k = 0; k < D; k++) acc = fmaf(su[k], W_glob[k * D + j], acc);
#pragma unroll 4
    for (int k = 0; k < D; k++) acc = fmaf(sm[k], W_glob[(D + k) * D + j], acc);
    float r = fmaxf(acc, 0.f);
    out_g[(size_t)g * OUTW + j] = r;
    g_u[g * D + j] = r;
}

// --------------------------------- launch ----------------------------------
extern "C" void kernel_launch(void* const* d_in, const int* in_sizes, int n_in,
                              void* d_out, int out_size) {
    const float* x      = (const float*)d_in[0];
    const int*   ei     = (const int*)d_in[1];
    const float* ea     = (const float*)d_in[2];
    const float* u      = (const float*)d_in[3];
    const int*   batch  = (const int*)d_in[4];
    const float* W_edge = (const float*)d_in[5];
    const float* b_edge = (const float*)d_in[6];
    const float* W_node = (const float*)d_in[7];
    const float* b_node = (const float*)d_in[8];
    const float* W_glob = (const float*)d_in[9];
    const float* b_glob = (const float*)d_in[10];

    const int* src = ei;
    const int* dstp = ei + N_EDGES;

    float* out   = (float*)d_out;
    float* out_x = out;                            // 50000 x 512
    float* out_g = out + (size_t)N_NODES * OUTW;   // 16 x 512

    const int MV_SMEM   = (2 * D * D + 8 * 8 * D) * 4;                       // 160 KB
    const int EDGE_SMEM = 16 * 8 * 32 * 16;                                  // 64 KB
    const int NODE_SMEM = (2 * D * D + N_GRAPHS * D + 8 * 8 * 2 * D) * 4;    // 200 KB

    cudaFuncSetAttribute(matvec_P_kernel, cudaFuncAttributeMaxDynamicSharedMemorySize, MV_SMEM);
    cudaFuncSetAttribute(edge_mma_kernel, cudaFuncAttributeMaxDynamicSharedMemorySize, EDGE_SMEM);
    cudaFuncSetAttribute(node_kernel,     cudaFuncAttributeMaxDynamicSharedMemorySize, NODE_SMEM);

    init_kernel<<<2048, 256>>>(x, u, out_x, out_g);
    hist_kernel<<<1024, 256>>>(dstp, batch);
    finalize_counts_kernel<<<256, 256>>>();
    scan_kernel<<<1, 1024>>>();
    scatter_kernel<<<1024, 256>>>(dstp);

    for (int t = 0; t < 3; t++) {
        const float* Xt = out_x + t * D;
        float*       Xn = out_x + (t + 1) * D;

        prep_u_kernel<<<32, 128>>>(W_edge, b_edge, W_node, b_node);
        matvec_P_kernel<<<148, 256, MV_SMEM>>>(Xt, W_edge, batch);
        edge_mma_kernel<<<296, 256, EDGE_SMEM>>>(t == 0 ? 1 : 0, ea, src, dstp,
                                                 W_edge + 2 * D * D);
        node_kernel<<<148, 256, NODE_SMEM>>>(Xt, Xn, batch, W_node);
        global_kernel<<<16, 128>>>(W_glob, b_glob, out_g + (t + 1) * D);
    }
}

// round 6
// speedup vs baseline: 1.0776x; 1.0776x over previous
#include <cuda_runtime.h>
#include <cstdint>

// ---------------------------------------------------------------------------
// MetaMLP (3-step GraphNet) on GB300 — mma.sync edge GEMM, dst-sorted edge
// layout (counting sort) => no aggregation atomics; node reads contiguous runs.
// ---------------------------------------------------------------------------

#define D 128
static constexpr int N_NODES  = 50000;
static constexpr int N_EDGES  = 800000;
static constexpr int N_GRAPHS = 16;
static constexpr int OUTW     = 4 * D;          // 512 output cols per row
static constexpr int N_TILES  = N_EDGES / 128;  // 6250

typedef unsigned long long u64;

// ------------------------- device scratch (no allocs) ----------------------
__device__ float g_ea  [(size_t)N_EDGES  * D];       // edge features, dst-sorted
__device__ float g_P12 [(size_t)N_NODES  * 2 * D];   // [P1+uW4b+b | P2]
__device__ float g_u    [N_GRAPHS * D];
__device__ float g_uWn3b[N_GRAPHS * D];
__device__ float g_gsum [N_GRAPHS * D];
__device__ float g_invN [N_NODES];
__device__ float g_invG [N_GRAPHS];
__device__ int   g_cnt  [N_NODES];     // zeroed at end of scan (replay invariant)
__device__ int   g_gcnt [N_GRAPHS];    // idem
__device__ int   g_rowptr[N_NODES + 1];
__device__ int   g_off  [N_NODES];
__device__ int   g_perm [N_EDGES];     // sorted pos -> original edge id
__device__ int   g_psrc [N_EDGES];     // src in sorted order
__device__ int   g_pdst [N_EDGES];     // dst in sorted order

// ------------------------------ helpers ------------------------------------
__device__ __forceinline__ u64 pack2(float a, float b) {
    u64 r; asm("mov.b64 %0, {%1, %2};" : "=l"(r) : "f"(a), "f"(b)); return r;
}
__device__ __forceinline__ float2 unpack2(u64 v) {
    float2 r; asm("mov.b64 {%0, %1}, %2;" : "=f"(r.x), "=f"(r.y) : "l"(v)); return r;
}
__device__ __forceinline__ void ffma2(u64& d, u64 a, u64 b) {
    asm("fma.rn.f32x2 %0, %1, %2, %3;" : "=l"(d) : "l"(a), "l"(b), "l"(d));
}
__device__ __forceinline__ uint32_t cvt_bf16x2(float a, float b) {
    uint32_t r;
    asm("cvt.rn.bf16x2.f32 %0, %1, %2;" : "=r"(r) : "f"(b), "f"(a));
    return r;
}
__device__ __forceinline__ void split2(float x, float y, uint32_t& hi, uint32_t& lo) {
    hi = cvt_bf16x2(x, y);
    float hx = __uint_as_float(hi << 16);
    float hy = __uint_as_float(hi & 0xffff0000u);
    lo = cvt_bf16x2(x - hx, y - hy);
}
__device__ __forceinline__ void mma_bf16(float* d, const uint32_t* a, uint32_t b0, uint32_t b1) {
    asm volatile("mma.sync.aligned.m16n8k16.row.col.f32.bf16.bf16.f32 "
        "{%0,%1,%2,%3}, {%4,%5,%6,%7}, {%8,%9}, {%0,%1,%2,%3};"
        : "+f"(d[0]), "+f"(d[1]), "+f"(d[2]), "+f"(d[3])
        : "r"(a[0]), "r"(a[1]), "r"(a[2]), "r"(a[3]), "r"(b0), "r"(b1));
}

// ------------------------------ hist (launch 0) -----------------------------
// g_cnt/g_gcnt are zero at entry (module-load zero-init; re-zeroed by scan).
__global__ void hist_kernel(const int* __restrict__ dst, const int* __restrict__ batch) {
    int stride = gridDim.x * blockDim.x;
    int tid0 = blockIdx.x * blockDim.x + threadIdx.x;
    for (int i = tid0; i < N_EDGES; i += stride) atomicAdd(&g_cnt[dst[i]], 1);
    for (int i = tid0; i < N_NODES; i += stride) atomicAdd(&g_gcnt[batch[i]], 1);
}

// ------------------------------ init (launch 1) -----------------------------
__global__ void init_kernel(const float* __restrict__ x, const float* __restrict__ u,
                            float* __restrict__ out_x, float* __restrict__ out_g) {
    int stride = gridDim.x * blockDim.x;
    int tid0 = blockIdx.x * blockDim.x + threadIdx.x;
    for (int i = tid0; i < N_NODES * D; i += stride) {
        int r = i >> 7, c = i & (D - 1);
        out_x[(size_t)r * OUTW + c] = x[i];
    }
    for (int i = tid0; i < N_GRAPHS * D; i += stride) {
        int r = i >> 7, c = i & (D - 1);
        out_g[(size_t)r * OUTW + c] = u[i];
        g_u[i] = u[i];
    }
}

// ----------------------- scan + finalize (launch 2) -------------------------
__global__ void scan_fin_kernel() {
    __shared__ int part[1024];
    const int NPT = (N_NODES + 1023) / 1024;   // 49
    int t = threadIdx.x;
    int base = t * NPT;
    int s = 0;
#pragma unroll 7
    for (int i = 0; i < NPT; i++) {
        int idx = base + i;
        if (idx < N_NODES) s += g_cnt[idx];
    }
    part[t] = s;
    __syncthreads();
    for (int off = 1; off < 1024; off <<= 1) {
        int v = (t >= off) ? part[t - off] : 0;
        __syncthreads();
        part[t] += v;
        __syncthreads();
    }
    int run = (t > 0) ? part[t - 1] : 0;
    for (int i = 0; i < NPT; i++) {
        int idx = base + i;
        if (idx < N_NODES) {
            int c = g_cnt[idx];
            g_rowptr[idx] = run;
            g_off[idx] = run;
            g_invN[idx] = 1.f / fmaxf((float)c, 1.f);
            g_cnt[idx] = 0;              // restore replay invariant
            run += c;
        }
    }
    if (t == 1023) g_rowptr[N_NODES] = part[1023];
    if (t < N_GRAPHS) {
        g_invG[t] = 1.f / fmaxf((float)g_gcnt[t], 1.f);
        g_gcnt[t] = 0;                   // restore replay invariant
    }
}

// ----------------------- matvec P1/P2 (launch 3, PROFILED) ------------------
// P1 = X@We1 + (u@We4 + b_edge)[batch]  ;  P2 = X@We2
// uW4b computed redundantly per block (16x128, K=128) into smem.
__global__ void __launch_bounds__(256) matvec_P_kernel(
    const float* __restrict__ X, const float* __restrict__ W_edge,
    const float* __restrict__ b_edge, const int* __restrict__ batch) {
    extern __shared__ float sh[];
    float* sW1 = sh;               // 16384
    float* sW2 = sh + 16384;       // 16384
    float* sV  = sh + 32768;       // 8192
    float* sGu = sh + 40960;       // 2048
    float* sUW = sh + 43008;       // 2048
    for (int i = threadIdx.x; i < D * D; i += blockDim.x) {
        sW1[i] = W_edge[i];
        sW2[i] = W_edge[D * D + i];
    }
    for (int i = threadIdx.x; i < N_GRAPHS * D; i += blockDim.x) sGu[i] = g_u[i];
    __syncthreads();
    // in-block uW4b: 256 threads, thread = (half, col j); each does 8 graphs
    {
        int j = threadIdx.x & 127, half = threadIdx.x >> 7;
        float acc[8];
#pragma unroll
        for (int q = 0; q < 8; q++) acc[q] = 0.f;
        const float* W4 = W_edge + 3 * D * D;
        for (int k = 0; k < D; k++) {
            float w = __ldg(W4 + k * D + j);
#pragma unroll
            for (int q = 0; q < 8; q++)
                acc[q] = fmaf(sGu[(half * 8 + q) * D + k], w, acc[q]);
        }
        float bj = __ldg(b_edge + j);
#pragma unroll
        for (int q = 0; q < 8; q++) sUW[(half * 8 + q) * D + j] = acc[q] + bj;
    }
    __syncthreads();
    int warp = threadIdx.x >> 5, lane = threadIdx.x & 31;
    float* myV = sV + warp * 8 * D;
    const int groups = N_NODES / 8;
    for (int grp = blockIdx.x * 8 + warp; grp < groups; grp += gridDim.x * 8) {
        int r0 = grp * 8;
#pragma unroll
        for (int e = 0; e < 8; e++) {
            float4 v = *((const float4*)(X + (size_t)(r0 + e) * OUTW) + lane);
            *((float4*)(myV + e * D) + lane) = v;
        }
        __syncwarp();
        u64 a0[8], a1[8], b0[8], b1[8];
#pragma unroll
        for (int e = 0; e < 8; e++) { a0[e] = a1[e] = b0[e] = b1[e] = 0ull; }
        for (int k = 0; k < D; k += 4) {
            ulonglong2 u0 = *((const ulonglong2*)(sW1 + (k + 0) * D) + lane);
            ulonglong2 u1 = *((const ulonglong2*)(sW1 + (k + 1) * D) + lane);
            ulonglong2 u2 = *((const ulonglong2*)(sW1 + (k + 2) * D) + lane);
            ulonglong2 u3 = *((const ulonglong2*)(sW1 + (k + 3) * D) + lane);
            ulonglong2 v0 = *((const ulonglong2*)(sW2 + (k + 0) * D) + lane);
            ulonglong2 v1 = *((const ulonglong2*)(sW2 + (k + 1) * D) + lane);
            ulonglong2 v2 = *((const ulonglong2*)(sW2 + (k + 2) * D) + lane);
            ulonglong2 v3 = *((const ulonglong2*)(sW2 + (k + 3) * D) + lane);
#pragma unroll
            for (int e = 0; e < 8; e++) {
                float4 a = *(const float4*)(myV + e * D + k);
                u64 p;
                p = pack2(a.x, a.x);
                ffma2(a0[e], p, u0.x); ffma2(a1[e], p, u0.y);
                ffma2(b0[e], p, v0.x); ffma2(b1[e], p, v0.y);
                p = pack2(a.y, a.y);
                ffma2(a0[e], p, u1.x); ffma2(a1[e], p, u1.y);
                ffma2(b0[e], p, v1.x); ffma2(b1[e], p, v1.y);
                p = pack2(a.z, a.z);
                ffma2(a0[e], p, u2.x); ffma2(a1[e], p, u2.y);
                ffma2(b0[e], p, v2.x); ffma2(b1[e], p, v2.y);
                p = pack2(a.w, a.w);
                ffma2(a0[e], p, u3.x); ffma2(a1[e], p, u3.y);
                ffma2(b0[e], p, v3.x); ffma2(b1[e], p, v3.y);
            }
        }
#pragma unroll
        for (int e = 0; e < 8; e++) {
            int g = __ldg(batch + r0 + e);
            float4 uv = *((const float4*)(sUW + g * D) + lane);
            float2 r01 = unpack2(a0[e]), r23 = unpack2(a1[e]);
            float2 s01 = unpack2(b0[e]), s23 = unpack2(b1[e]);
            float* base = g_P12 + (size_t)(r0 + e) * (2 * D);
            *((float4*)base + lane) =
                make_float4(r01.x + uv.x, r01.y + uv.y, r23.x + uv.z, r23.y + uv.w);
            *((float4*)(base + D) + lane) = make_float4(s01.x, s01.y, s23.x, s23.y);
        }
        __syncwarp();
    }
}

// ------------------------ scatter+permute (launch 4) ------------------------
__global__ void scatter_perm_kernel(const int* __restrict__ src, const int* __restrict__ dst) {
    int stride = gridDim.x * blockDim.x;
    for (int e = blockIdx.x * blockDim.x + threadIdx.x; e < N_EDGES; e += stride) {
        int d = dst[e];
        int p = atomicAdd(&g_off[d], 1);
        g_perm[p] = e;
        g_psrc[p] = src[e];
        g_pdst[p] = d;
    }
}

// ------------------------- edge kernel: mma.sync ----------------------------
// sorted layout: ea' = relu(ea@We3 + P1'[psrc] + P2[pdst]); plain stores.
__global__ void __launch_bounds__(256, 2) edge_mma_kernel(
    int step0, const float* __restrict__ ext_ea,
    const float* __restrict__ We3) {
    extern __shared__ uint4 sB[];   // [nt=16][ks=8][lane=32] -> {b0hi,b1hi,b0lo,b1lo}
    int tid = threadIdx.x;

    for (int i = tid; i < 16 * 8 * 32; i += 256) {
        int lane = i & 31, ks = (i >> 5) & 7, nt = i >> 8;
        int gid = lane >> 2, tig = lane & 3;
        int n  = nt * 8 + gid;
        int k0 = ks * 16 + tig * 2;
        float w00 = __ldg(We3 + k0 * D + n);
        float w01 = __ldg(We3 + (k0 + 1) * D + n);
        float w10 = __ldg(We3 + (k0 + 8) * D + n);
        float w11 = __ldg(We3 + (k0 + 9) * D + n);
        uint32_t b0h, b0l, b1h, b1l;
        split2(w00, w01, b0h, b0l);
        split2(w10, w11, b1h, b1l);
        sB[i] = make_uint4(b0h, b1h, b0l, b1l);
    }
    __syncthreads();

    int wid = tid >> 5, lane = tid & 31;
    int gid = lane >> 2, tig = lane & 3;
    int wm = wid & 3, wn = wid >> 2;
    const float* abase = step0 ? ext_ea : (const float*)g_ea;

    for (int tile = blockIdx.x; tile < N_TILES; tile += gridDim.x) {
        int r00 = tile * 128 + wm * 32 + gid;
        const float* pr[2][2];
#pragma unroll
        for (int mt = 0; mt < 2; mt++)
#pragma unroll
            for (int h = 0; h < 2; h++) {
                int r = r00 + mt * 16 + h * 8;
                int phys = step0 ? __ldg(&g_perm[r]) : r;
                pr[mt][h] = abase + (size_t)phys * D + tig * 2;
            }

        float acc[2][8][4];
#pragma unroll
        for (int mt = 0; mt < 2; mt++)
#pragma unroll
            for (int nt = 0; nt < 8; nt++)
#pragma unroll
                for (int q = 0; q < 4; q++) acc[mt][nt][q] = 0.f;

#pragma unroll
        for (int ks = 0; ks < 8; ks++) {
            uint32_t ah[2][4], al[2][4];
#pragma unroll
            for (int mt = 0; mt < 2; mt++) {
                float2 v0 = __ldg((const float2*)(pr[mt][0] + ks * 16));
                float2 v1 = __ldg((const float2*)(pr[mt][1] + ks * 16));
                float2 v2 = __ldg((const float2*)(pr[mt][0] + ks * 16 + 8));
                float2 v3 = __ldg((const float2*)(pr[mt][1] + ks * 16 + 8));
                split2(v0.x, v0.y, ah[mt][0], al[mt][0]);
                split2(v1.x, v1.y, ah[mt][1], al[mt][1]);
                split2(v2.x, v2.y, ah[mt][2], al[mt][2]);
                split2(v3.x, v3.y, ah[mt][3], al[mt][3]);
            }
#pragma unroll
            for (int nt = 0; nt < 8; nt++) {
                uint4 b = sB[((wn * 8 + nt) * 8 + ks) * 32 + lane];
#pragma unroll
                for (int mt = 0; mt < 2; mt++) {
                    mma_bf16(acc[mt][nt], ah[mt], b.x, b.y);   // Ahi * Whi
                    mma_bf16(acc[mt][nt], ah[mt], b.z, b.w);   // Ahi * Wlo
                    mma_bf16(acc[mt][nt], al[mt], b.x, b.y);   // Alo * Whi
                }
            }
        }

#pragma unroll
        for (int mt = 0; mt < 2; mt++) {
#pragma unroll
            for (int h = 0; h < 2; h++) {
                int r = r00 + mt * 16 + h * 8;
                int s = __ldg(&g_psrc[r]), d = __ldg(&g_pdst[r]);
                const float* p1b = g_P12 + (size_t)s * 256;
                const float* p2b = g_P12 + (size_t)d * 256 + 128;
                float* eo = g_ea + (size_t)r * D;
#pragma unroll
                for (int nt = 0; nt < 8; nt++) {
                    int c = wn * 64 + nt * 8 + tig * 2;
                    float2 p1 = __ldg((const float2*)(p1b + c));
                    float2 p2 = __ldg((const float2*)(p2b + c));
                    float rx = fmaxf(acc[mt][nt][h * 2 + 0] + p1.x + p2.x, 0.f);
                    float ry = fmaxf(acc[mt][nt][h * 2 + 1] + p1.y + p2.y, 0.f);
                    *(float2*)(eo + c) = make_float2(rx, ry);
                }
            }
        }
    }
}

// --------------------------- prep2 (uWn3b + gsum=0) -------------------------
__global__ void prep2_kernel(const float* __restrict__ W_node,
                             const float* __restrict__ b_node) {
    int g = blockIdx.x, j = threadIdx.x;
    __shared__ float su[D];
    su[j] = g_u[g * D + j];
    __syncthreads();
    const float* W3 = W_node + 2 * D * D;
    float acc = b_node[j];
#pragma unroll 8
    for (int k = 0; k < D; k++) acc = fmaf(su[k], W3[k * D + j], acc);
    g_uWn3b[g * D + j] = acc;
    g_gsum[g * D + j] = 0.f;
}

// ------------------------------- node kernel -------------------------------
// x' = relu([x, run_mean(ea')] @ Wn12 + uWn3b[batch]); contiguous CSR runs.
__global__ void __launch_bounds__(256) node_kernel(
    const float* __restrict__ Xin, float* __restrict__ Xout,
    const int* __restrict__ batch, const float* __restrict__ W_node) {
    extern __shared__ float sh[];
    float* sW = sh;
    float* sU = sh + 2 * D * D;
    float* sV = sU + N_GRAPHS * D;
    for (int i = threadIdx.x; i < 2 * D * D; i += blockDim.x) sW[i] = W_node[i];
    for (int i = threadIdx.x; i < N_GRAPHS * D; i += blockDim.x) sU[i] = g_uWn3b[i];
    __syncthreads();
    int warp = threadIdx.x >> 5, lane = threadIdx.x & 31;
    float* myV = sV + warp * 8 * (2 * D);
    const int groups = N_NODES / 8;
    for (int grp = blockIdx.x * 8 + warp; grp < groups; grp += gridDim.x * 8) {
        int r0 = grp * 8;
        int begNext = __ldg(&g_rowptr[r0]);
#pragma unroll
        for (int e = 0; e < 8; e++) {
            int row = r0 + e;
            float4 xv = *((const float4*)(Xin + (size_t)row * OUTW) + lane);
            *((float4*)(myV + e * 2 * D) + lane) = xv;
            int beg = begNext;
            begNext = __ldg(&g_rowptr[row + 1]);
            int end = begNext;
            // contiguous run of sorted edge features
            const float4* p = (const float4*)(g_ea + (size_t)beg * D) + lane;
            float4 av = make_float4(0.f, 0.f, 0.f, 0.f);
            int j = beg;
            for (; j + 1 < end; j += 2) {
                float4 v0 = __ldg(p);
                float4 v1 = __ldg(p + 32);
                p += 64;
                av.x += v0.x + v1.x; av.y += v0.y + v1.y;
                av.z += v0.z + v1.z; av.w += v0.w + v1.w;
            }
            if (j < end) {
                float4 v0 = __ldg(p);
                av.x += v0.x; av.y += v0.y; av.z += v0.z; av.w += v0.w;
            }
            float inv = __ldg(&g_invN[row]);
            av.x *= inv; av.y *= inv; av.z *= inv; av.w *= inv;
            *((float4*)(myV + e * 2 * D + D) + lane) = av;
        }
        __syncwarp();
        u64 acc0[8], acc1[8];
#pragma unroll
        for (int e = 0; e < 8; e++) { acc0[e] = 0ull; acc1[e] = 0ull; }
        for (int k = 0; k < 2 * D; k += 4) {
            ulonglong2 w0 = *((const ulonglong2*)(sW + (k + 0) * D) + lane);
            ulonglong2 w1 = *((const ulonglong2*)(sW + (k + 1) * D) + lane);
            ulonglong2 w2 = *((const ulonglong2*)(sW + (k + 2) * D) + lane);
            ulonglong2 w3 = *((const ulonglong2*)(sW + (k + 3) * D) + lane);
#pragma unroll
            for (int e = 0; e < 8; e++) {
                float4 a = *(const float4*)(myV + e * 2 * D + k);
                u64 p;
                p = pack2(a.x, a.x); ffma2(acc0[e], p, w0.x); ffma2(acc1[e], p, w0.y);
                p = pack2(a.y, a.y); ffma2(acc0[e], p, w1.x); ffma2(acc1[e], p, w1.y);
                p = pack2(a.z, a.z); ffma2(acc0[e], p, w2.x); ffma2(acc1[e], p, w2.y);
                p = pack2(a.w, a.w); ffma2(acc0[e], p, w3.x); ffma2(acc1[e], p, w3.y);
            }
        }
#pragma unroll
        for (int e = 0; e < 8; e++) {
            int row = r0 + e;
            int g = __ldg(batch + row);
            float4 ub = *((const float4*)(sU + g * D) + lane);
            float2 c01 = unpack2(acc0[e]), c23 = unpack2(acc1[e]);
            float4 r;
            r.x = fmaxf(c01.x + ub.x, 0.f);
            r.y = fmaxf(c01.y + ub.y, 0.f);
            r.z = fmaxf(c23.x + ub.z, 0.f);
            r.w = fmaxf(c23.y + ub.w, 0.f);
            *((float4*)(Xout + (size_t)row * OUTW) + lane) = r;
            atomicAdd((float4*)(g_gsum + g * D) + lane, r);
        }
        __syncwarp();
    }
}

// ------------------------------ global kernel ------------------------------
__global__ void global_kernel(const float* __restrict__ W_glob,
                              const float* __restrict__ b_glob,
                              float* __restrict__ out_g) {
    int g = blockIdx.x;
    int j = threadIdx.x;
    __shared__ float su[D], sm[D];
    su[j] = g_u[g * D + j];
    sm[j] = g_gsum[g * D + j] * g_invG[g];
    __syncthreads();
    float acc = b_glob[j];
#pragma unroll 4
    for (int k = 0; k < D; k++) acc = fmaf(su[k], W_glob[k * D + j], acc);
#pragma unroll 4
    for (int k = 0; k < D; k++) acc = fmaf(sm[k], W_glob[(D + k) * D + j], acc);
    float r = fmaxf(acc, 0.f);
    out_g[(size_t)g * OUTW + j] = r;
    g_u[g * D + j] = r;
}

// --------------------------------- launch ----------------------------------
extern "C" void kernel_launch(void* const* d_in, const int* in_sizes, int n_in,
                              void* d_out, int out_size) {
    const float* x      = (const float*)d_in[0];
    const int*   ei     = (const int*)d_in[1];
    const float* ea     = (const float*)d_in[2];
    const float* u      = (const float*)d_in[3];
    const int*   batch  = (const int*)d_in[4];
    const float* W_edge = (const float*)d_in[5];
    const float* b_edge = (const float*)d_in[6];
    const float* W_node = (const float*)d_in[7];
    const float* b_node = (const float*)d_in[8];
    const float* W_glob = (const float*)d_in[9];
    const float* b_glob = (const float*)d_in[10];

    const int* src = ei;
    const int* dstp = ei + N_EDGES;

    float* out   = (float*)d_out;
    float* out_x = out;                            // 50000 x 512
    float* out_g = out + (size_t)N_NODES * OUTW;   // 16 x 512

    const int MV_SMEM   = 45056 * 4;                                         // 176 KB
    const int EDGE_SMEM = 16 * 8 * 32 * 16;                                  // 64 KB
    const int NODE_SMEM = (2 * D * D + N_GRAPHS * D + 8 * 8 * 2 * D) * 4;    // 200 KB

    cudaFuncSetAttribute(matvec_P_kernel, cudaFuncAttributeMaxDynamicSharedMemorySize, MV_SMEM);
    cudaFuncSetAttribute(edge_mma_kernel, cudaFuncAttributeMaxDynamicSharedMemorySize, EDGE_SMEM);
    cudaFuncSetAttribute(node_kernel,     cudaFuncAttributeMaxDynamicSharedMemorySize, NODE_SMEM);

    // launch order chosen so index 3 (ncu capture point) = matvec_P_kernel
    hist_kernel<<<1024, 256>>>(dstp, batch);                          // 0
    init_kernel<<<2048, 256>>>(x, u, out_x, out_g);                   // 1
    scan_fin_kernel<<<1, 1024>>>();                                   // 2
    matvec_P_kernel<<<148, 256, MV_SMEM>>>(out_x, W_edge, b_edge, batch); // 3 (step 0)
    scatter_perm_kernel<<<1024, 256>>>(src, dstp);                    // 4

    for (int t = 0; t < 3; t++) {
        const float* Xt = out_x + t * D;
        float*       Xn = out_x + (t + 1) * D;
        if (t > 0)
            matvec_P_kernel<<<148, 256, MV_SMEM>>>(Xt, W_edge, b_edge, batch);
        edge_mma_kernel<<<296, 256, EDGE_SMEM>>>(t == 0 ? 1 : 0, ea, W_edge + 2 * D * D);
        prep2_kernel<<<16, 128>>>(W_node, b_node);
        node_kernel<<<148, 256, NODE_SMEM>>>(Xt, Xn, batch, W_node);
        global_kernel<<<16, 128>>>(W_glob, b_glob, out_g + (t + 1) * D);
    }
}

// round 7
// speedup vs baseline: 1.2887x; 1.1959x over previous
#include <cuda_runtime.h>
#include <cstdint>

// ---------------------------------------------------------------------------
// MetaMLP (3-step GraphNet) on GB300 — R4 structure (atomic agg) + pipelined
// A-loads in edge MMA, 16-warp matvec/node, uW4b folded into P1.
// ---------------------------------------------------------------------------

#define D 128
static constexpr int N_NODES  = 50000;
static constexpr int N_EDGES  = 800000;
static constexpr int N_GRAPHS = 16;
static constexpr int OUTW     = 4 * D;          // 512 output cols per row
static constexpr int N_TILES  = N_EDGES / 128;  // 6250

typedef unsigned long long u64;

// ------------------------- device scratch (no allocs) ----------------------
__device__ float g_ea  [(size_t)N_EDGES  * D];
__device__ float g_P12 [(size_t)N_NODES  * 2 * D];   // [P1+uW4b+b | P2]
__device__ float g_agg [(size_t)N_NODES  * D];
__device__ float g_u    [N_GRAPHS * D];
__device__ float g_uWn3b[N_GRAPHS * D];
__device__ float g_gsum [N_GRAPHS * D];
__device__ float g_invN [N_NODES];
__device__ float g_invG [N_GRAPHS];

// ------------------------------ helpers ------------------------------------
__device__ __forceinline__ u64 pack2(float a, float b) {
    u64 r; asm("mov.b64 %0, {%1, %2};" : "=l"(r) : "f"(a), "f"(b)); return r;
}
__device__ __forceinline__ float2 unpack2(u64 v) {
    float2 r; asm("mov.b64 {%0, %1}, %2;" : "=f"(r.x), "=f"(r.y) : "l"(v)); return r;
}
__device__ __forceinline__ void ffma2(u64& d, u64 a, u64 b) {
    asm("fma.rn.f32x2 %0, %1, %2, %3;" : "=l"(d) : "l"(a), "l"(b), "l"(d));
}
__device__ __forceinline__ uint32_t cvt_bf16x2(float a, float b) {
    uint32_t r;
    asm("cvt.rn.bf16x2.f32 %0, %1, %2;" : "=r"(r) : "f"(b), "f"(a));
    return r;
}
__device__ __forceinline__ void split2(float x, float y, uint32_t& hi, uint32_t& lo) {
    hi = cvt_bf16x2(x, y);
    float hx = __uint_as_float(hi << 16);
    float hy = __uint_as_float(hi & 0xffff0000u);
    lo = cvt_bf16x2(x - hx, y - hy);
}
__device__ __forceinline__ void mma_bf16(float* d, const uint32_t* a, uint32_t b0, uint32_t b1) {
    asm volatile("mma.sync.aligned.m16n8k16.row.col.f32.bf16.bf16.f32 "
        "{%0,%1,%2,%3}, {%4,%5,%6,%7}, {%8,%9}, {%0,%1,%2,%3};"
        : "+f"(d[0]), "+f"(d[1]), "+f"(d[2]), "+f"(d[3])
        : "r"(a[0]), "r"(a[1]), "r"(a[2]), "r"(a[3]), "r"(b0), "r"(b1));
}
__device__ __forceinline__ void red_add2(float* addr, float x, float y) {
    asm volatile("red.global.add.v2.f32 [%0], {%1, %2};"
                 :: "l"(addr), "f"(x), "f"(y) : "memory");
}

// ------------------------------ init (launch 0) -----------------------------
__global__ void init_kernel(const float* __restrict__ x, const float* __restrict__ u,
                            float* __restrict__ out_x, float* __restrict__ out_g) {
    int stride = gridDim.x * blockDim.x;
    int tid0 = blockIdx.x * blockDim.x + threadIdx.x;
    for (int i = tid0; i < N_NODES * D; i += stride) {
        int r = i >> 7, c = i & (D - 1);
        out_x[(size_t)r * OUTW + c] = x[i];
        g_agg[i] = 0.f;
    }
    for (int i = tid0; i < N_GRAPHS * D; i += stride) {
        int r = i >> 7, c = i & (D - 1);
        out_g[(size_t)r * OUTW + c] = u[i];
        g_u[i] = u[i];
    }
    for (int i = tid0; i < N_NODES; i += stride) g_invN[i] = 0.f;
    for (int i = tid0; i < N_GRAPHS; i += stride) g_invG[i] = 0.f;
}

// ------------------------------ hist / finalize ------------------------------
__global__ void hist_kernel(const int* __restrict__ dst, const int* __restrict__ batch) {
    int stride = gridDim.x * blockDim.x;
    int tid0 = blockIdx.x * blockDim.x + threadIdx.x;
    for (int i = tid0; i < N_EDGES; i += stride) atomicAdd(&g_invN[dst[i]], 1.f);
    for (int i = tid0; i < N_NODES; i += stride) atomicAdd(&g_invG[batch[i]], 1.f);
}

__global__ void finalize_counts_kernel() {
    int stride = gridDim.x * blockDim.x;
    int tid0 = blockIdx.x * blockDim.x + threadIdx.x;
    for (int i = tid0; i < N_NODES; i += stride) g_invN[i] = 1.f / fmaxf(g_invN[i], 1.f);
    for (int i = tid0; i < N_GRAPHS; i += stride) g_invG[i] = 1.f / fmaxf(g_invG[i], 1.f);
}

// ----------------------- matvec P1/P2 (512 thr, 16 warps) -------------------
// P1 = X@We1 + (u@We4 + b_edge)[batch]  ;  P2 = X@We2
__global__ void __launch_bounds__(512) matvec_P_kernel(
    const float* __restrict__ X, const float* __restrict__ W_edge,
    const float* __restrict__ b_edge, const int* __restrict__ batch) {
    extern __shared__ float sh[];
    float* sW1 = sh;               // 16384 f
    float* sW2 = sh + 16384;       // 16384 f
    float* sV  = sh + 32768;       // 16 warps * 8 rows * 128 = 16384 f
    float* sGu = sh + 49152;       // 2048 f
    float* sUW = sh + 51200;       // 2048 f
    for (int i = threadIdx.x; i < D * D; i += blockDim.x) {
        sW1[i] = W_edge[i];
        sW2[i] = W_edge[D * D + i];
    }
    for (int i = threadIdx.x; i < N_GRAPHS * D; i += blockDim.x) sGu[i] = g_u[i];
    __syncthreads();
    // in-block uW4b: thread = (quad q4, col j); each quad handles 4 graphs
    {
        int j = threadIdx.x & 127, q4 = threadIdx.x >> 7;
        float acc[4];
#pragma unroll
        for (int q = 0; q < 4; q++) acc[q] = 0.f;
        const float* W4 = W_edge + 3 * D * D;
        for (int k = 0; k < D; k++) {
            float w = __ldg(W4 + k * D + j);
#pragma unroll
            for (int q = 0; q < 4; q++)
                acc[q] = fmaf(sGu[(q4 * 4 + q) * D + k], w, acc[q]);
        }
        float bj = __ldg(b_edge + j);
#pragma unroll
        for (int q = 0; q < 4; q++) sUW[(q4 * 4 + q) * D + j] = acc[q] + bj;
    }
    __syncthreads();
    int warp = threadIdx.x >> 5, lane = threadIdx.x & 31;
    float* myV = sV + warp * 8 * D;
    const int groups = N_NODES / 8;
    for (int grp = blockIdx.x * 16 + warp; grp < groups; grp += gridDim.x * 16) {
        int r0 = grp * 8;
#pragma unroll
        for (int e = 0; e < 8; e++) {
            float4 v = *((const float4*)(X + (size_t)(r0 + e) * OUTW) + lane);
            *((float4*)(myV + e * D) + lane) = v;
        }
        __syncwarp();
        u64 a0[8], a1[8], b0[8], b1[8];
#pragma unroll
        for (int e = 0; e < 8; e++) { a0[e] = a1[e] = b0[e] = b1[e] = 0ull; }
        for (int k = 0; k < D; k += 4) {
            ulonglong2 u0 = *((const ulonglong2*)(sW1 + (k + 0) * D) + lane);
            ulonglong2 u1 = *((const ulonglong2*)(sW1 + (k + 1) * D) + lane);
            ulonglong2 u2 = *((const ulonglong2*)(sW1 + (k + 2) * D) + lane);
            ulonglong2 u3 = *((const ulonglong2*)(sW1 + (k + 3) * D) + lane);
            ulonglong2 v0 = *((const ulonglong2*)(sW2 + (k + 0) * D) + lane);
            ulonglong2 v1 = *((const ulonglong2*)(sW2 + (k + 1) * D) + lane);
            ulonglong2 v2 = *((const ulonglong2*)(sW2 + (k + 2) * D) + lane);
            ulonglong2 v3 = *((const ulonglong2*)(sW2 + (k + 3) * D) + lane);
#pragma unroll
            for (int e = 0; e < 8; e++) {
                float4 a = *(const float4*)(myV + e * D + k);
                u64 p;
                p = pack2(a.x, a.x);
                ffma2(a0[e], p, u0.x); ffma2(a1[e], p, u0.y);
                ffma2(b0[e], p, v0.x); ffma2(b1[e], p, v0.y);
                p = pack2(a.y, a.y);
                ffma2(a0[e], p, u1.x); ffma2(a1[e], p, u1.y);
                ffma2(b0[e], p, v1.x); ffma2(b1[e], p, v1.y);
                p = pack2(a.z, a.z);
                ffma2(a0[e], p, u2.x); ffma2(a1[e], p, u2.y);
                ffma2(b0[e], p, v2.x); ffma2(b1[e], p, v2.y);
                p = pack2(a.w, a.w);
                ffma2(a0[e], p, u3.x); ffma2(a1[e], p, u3.y);
                ffma2(b0[e], p, v3.x); ffma2(b1[e], p, v3.y);
            }
        }
#pragma unroll
        for (int e = 0; e < 8; e++) {
            int g = __ldg(batch + r0 + e);
            float4 uv = *((const float4*)(sUW + g * D) + lane);
            float2 r01 = unpack2(a0[e]), r23 = unpack2(a1[e]);
            float2 s01 = unpack2(b0[e]), s23 = unpack2(b1[e]);
            float* base = g_P12 + (size_t)(r0 + e) * (2 * D);
            *((float4*)base + lane) =
                make_float4(r01.x + uv.x, r01.y + uv.y, r23.x + uv.z, r23.y + uv.w);
            *((float4*)(base + D) + lane) = make_float4(s01.x, s01.y, s23.x, s23.y);
        }
        __syncwarp();
    }
}

// ------------------------- edge kernel: mma.sync ----------------------------
// ea' = relu(ea@We3 + P1'[src] + P2[dst]); red-add to agg. Pipelined A loads.
__global__ void __launch_bounds__(256, 2) edge_mma_kernel(
    int step0, int store_ea, const float* __restrict__ ext_ea,
    const int* __restrict__ src, const int* __restrict__ dst,
    const float* __restrict__ We3) {
    extern __shared__ uint4 sB[];   // [nt=16][ks=8][lane=32] -> {b0hi,b1hi,b0lo,b1lo}
    int tid = threadIdx.x;

    for (int i = tid; i < 16 * 8 * 32; i += 256) {
        int lane = i & 31, ks = (i >> 5) & 7, nt = i >> 8;
        int gid = lane >> 2, tig = lane & 3;
        int n  = nt * 8 + gid;
        int k0 = ks * 16 + tig * 2;
        float w00 = __ldg(We3 + k0 * D + n);
        float w01 = __ldg(We3 + (k0 + 1) * D + n);
        float w10 = __ldg(We3 + (k0 + 8) * D + n);
        float w11 = __ldg(We3 + (k0 + 9) * D + n);
        uint32_t b0h, b0l, b1h, b1l;
        split2(w00, w01, b0h, b0l);
        split2(w10, w11, b1h, b1l);
        sB[i] = make_uint4(b0h, b1h, b0l, b1l);
    }
    __syncthreads();

    int wid = tid >> 5, lane = tid & 31;
    int gid = lane >> 2, tig = lane & 3;
    int wm = wid & 3, wn = wid >> 2;
    const float* ea_in = step0 ? ext_ea : (const float*)g_ea;

    for (int tile = blockIdx.x; tile < N_TILES; tile += gridDim.x) {
        const float* A = ea_in + (size_t)tile * (128 * 128);
        const float* base0 = A + (wm * 32 + 0 * 16 + gid) * 128 + tig * 2;
        const float* base1 = A + (wm * 32 + 1 * 16 + gid) * 128 + tig * 2;

        // prefetch edge endpoints for epilogue
        int sidx[2][2], didx[2][2];
#pragma unroll
        for (int mt = 0; mt < 2; mt++)
#pragma unroll
            for (int h = 0; h < 2; h++) {
                int r = tile * 128 + wm * 32 + mt * 16 + h * 8 + gid;
                sidx[mt][h] = __ldg(src + r);
                didx[mt][h] = __ldg(dst + r);
            }

        float acc[2][8][4];
#pragma unroll
        for (int mt = 0; mt < 2; mt++)
#pragma unroll
            for (int nt = 0; nt < 8; nt++)
#pragma unroll
                for (int q = 0; q < 4; q++) acc[mt][nt][q] = 0.f;

        // software-pipelined A loads: cur holds ks, nxt prefetches ks+1
        float2 cur[2][4], nxt[2][4];
#pragma unroll
        for (int mt = 0; mt < 2; mt++) {
            const float* b = mt ? base1 : base0;
            cur[mt][0] = __ldg((const float2*)b);
            cur[mt][1] = __ldg((const float2*)(b + 8 * 128));
            cur[mt][2] = __ldg((const float2*)(b + 8));
            cur[mt][3] = __ldg((const float2*)(b + 8 * 128 + 8));
        }
#pragma unroll
        for (int ks = 0; ks < 8; ks++) {
            if (ks < 7) {
#pragma unroll
                for (int mt = 0; mt < 2; mt++) {
                    const float* b = (mt ? base1 : base0) + (ks + 1) * 16;
                    nxt[mt][0] = __ldg((const float2*)b);
                    nxt[mt][1] = __ldg((const float2*)(b + 8 * 128));
                    nxt[mt][2] = __ldg((const float2*)(b + 8));
                    nxt[mt][3] = __ldg((const float2*)(b + 8 * 128 + 8));
                }
            }
            uint32_t ah[2][4], al[2][4];
#pragma unroll
            for (int mt = 0; mt < 2; mt++)
#pragma unroll
                for (int q = 0; q < 4; q++)
                    split2(cur[mt][q].x, cur[mt][q].y, ah[mt][q], al[mt][q]);
#pragma unroll
            for (int nt = 0; nt < 8; nt++) {
                uint4 b = sB[((wn * 8 + nt) * 8 + ks) * 32 + lane];
#pragma unroll
                for (int mt = 0; mt < 2; mt++) {
                    mma_bf16(acc[mt][nt], ah[mt], b.x, b.y);   // Ahi * Whi
                    mma_bf16(acc[mt][nt], ah[mt], b.z, b.w);   // Ahi * Wlo
                    mma_bf16(acc[mt][nt], al[mt], b.x, b.y);   // Alo * Whi
                }
            }
#pragma unroll
            for (int mt = 0; mt < 2; mt++)
#pragma unroll
                for (int q = 0; q < 4; q++) cur[mt][q] = nxt[mt][q];
        }

#pragma unroll
        for (int mt = 0; mt < 2; mt++) {
#pragma unroll
            for (int h = 0; h < 2; h++) {
                int r = tile * 128 + wm * 32 + mt * 16 + h * 8 + gid;
                int s = sidx[mt][h], d = didx[mt][h];
                const float* p1b = g_P12 + (size_t)s * 256;
                const float* p2b = g_P12 + (size_t)d * 256 + 128;
                float* eo = g_ea + (size_t)r * D;
                float* ao = g_agg + (size_t)d * D;
#pragma unroll
                for (int nt = 0; nt < 8; nt++) {
                    int c = wn * 64 + nt * 8 + tig * 2;
                    float2 p1 = __ldg((const float2*)(p1b + c));
                    float2 p2 = __ldg((const float2*)(p2b + c));
                    float rx = fmaxf(acc[mt][nt][h * 2 + 0] + p1.x + p2.x, 0.f);
                    float ry = fmaxf(acc[mt][nt][h * 2 + 1] + p1.y + p2.y, 0.f);
                    if (store_ea) *(float2*)(eo + c) = make_float2(rx, ry);
                    red_add2(ao + c, rx, ry);
                }
            }
        }
    }
}

// --------------------------- prep2 (uWn3b + gsum=0) -------------------------
__global__ void prep2_kernel(const float* __restrict__ W_node,
                             const float* __restrict__ b_node) {
    int g = blockIdx.x, j = threadIdx.x;
    __shared__ float su[D];
    su[j] = g_u[g * D + j];
    __syncthreads();
    const float* W3 = W_node + 2 * D * D;
    float acc = b_node[j];
#pragma unroll 8
    for (int k = 0; k < D; k++) acc = fmaf(su[k], W3[k * D + j], acc);
    g_uWn3b[g * D + j] = acc;
    g_gsum[g * D + j] = 0.f;
}

// ------------------------- node kernel (512 thr, 16 warps) ------------------
// x' = relu([x, agg/deg] @ Wn12 + uWn3b[batch]); zeroes agg for next step.
__global__ void __launch_bounds__(512) node_kernel(
    const float* __restrict__ Xin, float* __restrict__ Xout,
    const int* __restrict__ batch, const float* __restrict__ W_node) {
    extern __shared__ float sh[];
    float* sW = sh;                       // 32768 f
    float* sU = sh + 2 * D * D;           // 2048 f
    float* sV = sU + N_GRAPHS * D;        // 16 warps * 4 rows * 256 = 16384 f
    for (int i = threadIdx.x; i < 2 * D * D; i += blockDim.x) sW[i] = W_node[i];
    for (int i = threadIdx.x; i < N_GRAPHS * D; i += blockDim.x) sU[i] = g_uWn3b[i];
    __syncthreads();
    int warp = threadIdx.x >> 5, lane = threadIdx.x & 31;
    float* myV = sV + warp * 4 * (2 * D);
    const int groups = N_NODES / 4;   // 12500
    for (int grp = blockIdx.x * 16 + warp; grp < groups; grp += gridDim.x * 16) {
        int r0 = grp * 4;
#pragma unroll
        for (int e = 0; e < 4; e++) {
            int row = r0 + e;
            float4 xv = *((const float4*)(Xin + (size_t)row * OUTW) + lane);
            *((float4*)(myV + e * 2 * D) + lane) = xv;
            float inv = __ldg(&g_invN[row]);
            float4 av = *((const float4*)(g_agg + (size_t)row * D) + lane);
            *((float4*)(g_agg + (size_t)row * D) + lane) = make_float4(0.f, 0.f, 0.f, 0.f);
            av.x *= inv; av.y *= inv; av.z *= inv; av.w *= inv;
            *((float4*)(myV + e * 2 * D + D) + lane) = av;
        }
        __syncwarp();
        u64 acc0[4], acc1[4];
#pragma unroll
        for (int e = 0; e < 4; e++) { acc0[e] = 0ull; acc1[e] = 0ull; }
        for (int k = 0; k < 2 * D; k += 4) {
            ulonglong2 w0 = *((const ulonglong2*)(sW + (k + 0) * D) + lane);
            ulonglong2 w1 = *((const ulonglong2*)(sW + (k + 1) * D) + lane);
            ulonglong2 w2 = *((const ulonglong2*)(sW + (k + 2) * D) + lane);
            ulonglong2 w3 = *((const ulonglong2*)(sW + (k + 3) * D) + lane);
#pragma unroll
            for (int e = 0; e < 4; e++) {
                float4 a = *(const float4*)(myV + e * 2 * D + k);
                u64 p;
                p = pack2(a.x, a.x); ffma2(acc0[e], p, w0.x); ffma2(acc1[e], p, w0.y);
                p = pack2(a.y, a.y); ffma2(acc0[e], p, w1.x); ffma2(acc1[e], p, w1.y);
                p = pack2(a.z, a.z); ffma2(acc0[e], p, w2.x); ffma2(acc1[e], p, w2.y);
                p = pack2(a.w, a.w); ffma2(acc0[e], p, w3.x); ffma2(acc1[e], p, w3.y);
            }
        }
#pragma unroll
        for (int e = 0; e < 4; e++) {
            int row = r0 + e;
            int g = __ldg(batch + row);
            float4 ub = *((const float4*)(sU + g * D) + lane);
            float2 c01 = unpack2(acc0[e]), c23 = unpack2(acc1[e]);
            float4 r;
            r.x = fmaxf(c01.x + ub.x, 0.f);
            r.y = fmaxf(c01.y + ub.y, 0.f);
            r.z = fmaxf(c23.x + ub.z, 0.f);
            r.w = fmaxf(c23.y + ub.w, 0.f);
            *((float4*)(Xout + (size_t)row * OUTW) + lane) = r;
            atomicAdd((float4*)(g_gsum + g * D) + lane, r);
        }
        __syncwarp();
    }
}

// ------------------------------ global kernel ------------------------------
__global__ void global_kernel(const float* __restrict__ W_glob,
                              const float* __restrict__ b_glob,
                              float* __restrict__ out_g) {
    int g = blockIdx.x;
    int j = threadIdx.x;
    __shared__ float su[D], sm[D];
    su[j] = g_u[g * D + j];
    sm[j] = g_gsum[g * D + j] * g_invG[g];
    __syncthreads();
    float acc = b_glob[j];
#pragma unroll 4
    for (int k = 0; k < D; k++) acc = fmaf(su[k], W_glob[k * D + j], acc);
#pragma unroll 4
    for (int k = 0; k < D; k++) acc = fmaf(sm[k], W_glob[(D + k) * D + j], acc);
    float r = fmaxf(acc, 0.f);
    out_g[(size_t)g * OUTW + j] = r;
    g_u[g * D + j] = r;
}

// --------------------------------- launch ----------------------------------
extern "C" void kernel_launch(void* const* d_in, const int* in_sizes, int n_in,
                              void* d_out, int out_size) {
    const float* x      = (const float*)d_in[0];
    const int*   ei     = (const int*)d_in[1];
    const float* ea     = (const float*)d_in[2];
    const float* u      = (const float*)d_in[3];
    const int*   batch  = (const int*)d_in[4];
    const float* W_edge = (const float*)d_in[5];
    const float* b_edge = (const float*)d_in[6];
    const float* W_node = (const float*)d_in[7];
    const float* b_node = (const float*)d_in[8];
    const float* W_glob = (const float*)d_in[9];
    const float* b_glob = (const float*)d_in[10];

    const int* src = ei;
    const int* dstp = ei + N_EDGES;

    float* out   = (float*)d_out;
    float* out_x = out;                            // 50000 x 512
    float* out_g = out + (size_t)N_NODES * OUTW;   // 16 x 512

    const int MV_SMEM   = 53248 * 4;               // 208 KB
    const int EDGE_SMEM = 16 * 8 * 32 * 16;        // 64 KB
    const int NODE_SMEM = (2 * D * D + N_GRAPHS * D + 16 * 4 * 2 * D) * 4;  // 200 KB

    cudaFuncSetAttribute(matvec_P_kernel, cudaFuncAttributeMaxDynamicSharedMemorySize, MV_SMEM);
    cudaFuncSetAttribute(edge_mma_kernel, cudaFuncAttributeMaxDynamicSharedMemorySize, EDGE_SMEM);
    cudaFuncSetAttribute(node_kernel,     cudaFuncAttributeMaxDynamicSharedMemorySize, NODE_SMEM);

    // launch order: index 3 (ncu capture point) = edge_mma_kernel
    init_kernel<<<2048, 256>>>(x, u, out_x, out_g);                        // 0
    matvec_P_kernel<<<148, 512, MV_SMEM>>>(out_x, W_edge, b_edge, batch);  // 1 (t=0)
    hist_kernel<<<1024, 256>>>(dstp, batch);                               // 2
    edge_mma_kernel<<<296, 256, EDGE_SMEM>>>(1, 1, ea, src, dstp,          // 3 PROFILED
                                             W_edge + 2 * D * D);
    finalize_counts_kernel<<<256, 256>>>();                                // 4

    for (int t = 0; t < 3; t++) {
        const float* Xt = out_x + t * D;
        float*       Xn = out_x + (t + 1) * D;

        prep2_kernel<<<16, 128>>>(W_node, b_node);
        node_kernel<<<148, 512, NODE_SMEM>>>(Xt, Xn, batch, W_node);
        global_kernel<<<16, 128>>>(W_glob, b_glob, out_g + (t + 1) * D);

        if (t < 2) {
            matvec_P_kernel<<<148, 512, MV_SMEM>>>(Xn, W_edge, b_edge, batch);
            edge_mma_kernel<<<296, 256, EDGE_SMEM>>>(0, (t + 1) < 2 ? 1 : 0, ea,
                                                     src, dstp, W_edge + 2 * D * D);
        }
    }
}